// round 1
// baseline (speedup 1.0000x reference)
#include <cuda_runtime.h>
#include <cuda_bf16.h>

#define WARPS_PER_CTA 8

__device__ __forceinline__ float leaky02(float x) { return fmaxf(x, 0.2f * x); }

__global__ __launch_bounds__(WARPS_PER_CTA * 32)
void flatnet_warp_row_kernel(
    const float* __restrict__ pgi,
    const float* __restrict__ W_lift, const float* __restrict__ b_lift,
    const float* __restrict__ W_code, const float* __restrict__ b_code,
    const float* __restrict__ W_h1,   const float* __restrict__ b_h1,
    const float* __restrict__ W_h2,   const float* __restrict__ b_h2,
    const float* __restrict__ W_h3,   const float* __restrict__ b_h3,
    const float* __restrict__ W_h4,   const float* __restrict__ b_h4,
    float* __restrict__ out)
{
    // Per-warp ping-pong scratch:
    //   A: 192 floats (8x8 points xyz, later 128-wide activations)
    //   B: 128 floats (v[96], later 64/16-wide activations)
    __shared__ float smA[WARPS_PER_CTA][192];
    __shared__ float smB[WARPS_PER_CTA][128];

    const int warp = threadIdx.x >> 5;
    const int lane = threadIdx.x & 31;
    const int row  = blockIdx.x * WARPS_PER_CTA + warp;   // row = b*1024 + g
    const int b  = row >> 10;
    const int g  = row & 1023;
    const int gi = g >> 5;
    const int gj = g & 31;

    float* A  = smA[warp];
    float* Bf = smB[warp];

    // ---- Load the 8x8 block of points (each grid row = 24 contiguous floats) ----
    // flat point index m = (gi*8 + r)*256 + (gj*8 + c); element = pgi[(b*65536 + m)*3 + ...]
    const float* base = pgi + ((size_t)b * 65536 + (size_t)(gi * 8) * 256 + (size_t)(gj * 8)) * 3;
    if (lane < 24) {
        #pragma unroll
        for (int r = 0; r < 8; r++)
            A[r * 24 + lane] = base[(size_t)r * 768 + lane];
    }
    __syncwarp();

    // ---- Lift: lane = channel c in [0,32). Loop all 64 points (smem broadcast). ----
    const float w0 = __ldg(W_lift + lane);
    const float w1 = __ldg(W_lift + 32 + lane);
    const float w2 = __ldg(W_lift + 64 + lane);
    const float bl = __ldg(b_lift + lane);

    float mInner = -1e30f, mInter = -1e30f, mOuter = -1e30f;
    #pragma unroll
    for (int p = 0; p < 64; p++) {
        const int r = p >> 3, c = p & 7;
        const float x = A[p * 3 + 0];
        const float y = A[p * 3 + 1];
        const float z = A[p * 3 + 2];
        float h = fmaf(x, w0, fmaf(y, w1, fmaf(z, w2, bl)));
        h = leaky02(h);
        const int d = min(min(r, c), min(7 - r, 7 - c));   // compile-time per p (fully unrolled)
        if (d == 3)      mInner = fmaxf(mInner, h);
        else if (d == 2) mInter = fmaxf(mInter, h);
        else             mOuter = fmaxf(mOuter, h);
    }
    __syncwarp();
    // v = [inner(32) | inter(32) | outer(32)]
    Bf[lane]      = mInner;
    Bf[32 + lane] = mInter;
    Bf[64 + lane] = mOuter;
    __syncwarp();

    // ---- v_code[128] = leaky(v @ W_code + b_code); lane owns j, j+32, j+64, j+96 ----
    float a0 = __ldg(b_code + lane);
    float a1 = __ldg(b_code + 32 + lane);
    float a2 = __ldg(b_code + 64 + lane);
    float a3 = __ldg(b_code + 96 + lane);
    #pragma unroll 4
    for (int i = 0; i < 96; i++) {
        const float vi = Bf[i];                 // smem broadcast
        const float* wr = W_code + i * 128 + lane;
        a0 = fmaf(vi, __ldg(wr),      a0);
        a1 = fmaf(vi, __ldg(wr + 32), a1);
        a2 = fmaf(vi, __ldg(wr + 64), a2);
        a3 = fmaf(vi, __ldg(wr + 96), a3);
    }
    __syncwarp();
    A[lane]      = leaky02(a0);
    A[32 + lane] = leaky02(a1);
    A[64 + lane] = leaky02(a2);
    A[96 + lane] = leaky02(a3);
    __syncwarp();

    // ---- h1[64] = relu(v_code @ W_h1 + b_h1); lane owns j, j+32 ----
    float c0 = __ldg(b_h1 + lane);
    float c1 = __ldg(b_h1 + 32 + lane);
    #pragma unroll 4
    for (int i = 0; i < 128; i++) {
        const float vi = A[i];
        const float* wr = W_h1 + i * 64 + lane;
        c0 = fmaf(vi, __ldg(wr),      c0);
        c1 = fmaf(vi, __ldg(wr + 32), c1);
    }
    Bf[lane]      = fmaxf(c0, 0.0f);
    Bf[32 + lane] = fmaxf(c1, 0.0f);
    __syncwarp();

    // ---- h2[32] = relu(h1 @ W_h2 + b_h2); lane owns j ----
    float e0 = __ldg(b_h2 + lane);
    #pragma unroll 8
    for (int i = 0; i < 64; i++)
        e0 = fmaf(Bf[i], __ldg(W_h2 + i * 32 + lane), e0);
    A[lane] = fmaxf(e0, 0.0f);
    __syncwarp();

    // ---- h3[16] = relu(h2 @ W_h3 + b_h3); lanes 0..15 ----
    if (lane < 16) {
        float f0 = __ldg(b_h3 + lane);
        #pragma unroll 8
        for (int i = 0; i < 32; i++)
            f0 = fmaf(A[i], __ldg(W_h3 + i * 16 + lane), f0);
        Bf[lane] = fmaxf(f0, 0.0f);
    }
    __syncwarp();

    // ---- out[3] = h3 @ W_h4 + b_h4; lanes 0..2 ----
    if (lane < 3) {
        float o = __ldg(b_h4 + lane);
        #pragma unroll
        for (int i = 0; i < 16; i++)
            o = fmaf(Bf[i], __ldg(W_h4 + i * 3 + lane), o);
        out[(size_t)row * 3 + lane] = o;
    }
}

extern "C" void kernel_launch(void* const* d_in, const int* in_sizes, int n_in,
                              void* d_out, int out_size)
{
    const float* pgi    = (const float*)d_in[0];
    const float* W_lift = (const float*)d_in[1];
    const float* b_lift = (const float*)d_in[2];
    const float* W_code = (const float*)d_in[3];
    const float* b_code = (const float*)d_in[4];
    const float* W_h1   = (const float*)d_in[5];
    const float* b_h1   = (const float*)d_in[6];
    const float* W_h2   = (const float*)d_in[7];
    const float* b_h2   = (const float*)d_in[8];
    const float* W_h3   = (const float*)d_in[9];
    const float* b_h3   = (const float*)d_in[10];
    const float* W_h4   = (const float*)d_in[11];
    const float* b_h4   = (const float*)d_in[12];
    float* out = (float*)d_out;

    // 32768 rows (b,g), 1 warp per row, 8 warps per CTA -> 4096 CTAs
    flatnet_warp_row_kernel<<<4096, WARPS_PER_CTA * 32>>>(
        pgi, W_lift, b_lift, W_code, b_code,
        W_h1, b_h1, W_h2, b_h2, W_h3, b_h3, W_h4, b_h4, out);
}

// round 2
// speedup vs baseline: 1.9456x; 1.9456x over previous
#include <cuda_runtime.h>
#include <cuda_bf16.h>
#include <cstdint>

#define WARPS_PER_CTA 8
#define ROWS_PER_WARP 4
// per-warp scratch: [0,1024) points (4 rows x 64 x float4) -> later activations
//                   [1024,1408) v[96][4] -> later h1[64][4] / h3[16][4]
#define BUF_FLOATS 1408

typedef unsigned long long u64;

__device__ __forceinline__ u64 fma2(u64 a, u64 b, u64 c) {
    u64 d;
    asm("fma.rn.f32x2 %0, %1, %2, %3;" : "=l"(d) : "l"(a), "l"(b), "l"(c));
    return d;
}
__device__ __forceinline__ u64 pack2(float x, float y) {
    u64 d;
    asm("mov.b64 %0, {%1, %2};" : "=l"(d) : "r"(__float_as_uint(x)), "r"(__float_as_uint(y)));
    return d;
}
__device__ __forceinline__ void unpack2(u64 a, float& x, float& y) {
    unsigned lo, hi;
    asm("mov.b64 {%0, %1}, %2;" : "=r"(lo), "=r"(hi) : "l"(a));
    x = __uint_as_float(lo); y = __uint_as_float(hi);
}
__device__ __forceinline__ float leaky02(float x) { return fmaxf(x, 0.2f * x); }

__global__ __launch_bounds__(WARPS_PER_CTA * 32)
void flatnet_r4_kernel(
    const float* __restrict__ pgi,
    const float* __restrict__ W_lift, const float* __restrict__ b_lift,
    const float* __restrict__ W_code, const float* __restrict__ b_code,
    const float* __restrict__ W_h1,   const float* __restrict__ b_h1,
    const float* __restrict__ W_h2,   const float* __restrict__ b_h2,
    const float* __restrict__ W_h3,   const float* __restrict__ b_h3,
    const float* __restrict__ W_h4,   const float* __restrict__ b_h4,
    float* __restrict__ out)
{
    __shared__ __align__(16) float sbuf[WARPS_PER_CTA][BUF_FLOATS];

    const int warp = threadIdx.x >> 5;
    const int lane = threadIdx.x & 31;
    const int wrow = (blockIdx.x * WARPS_PER_CTA + warp) * ROWS_PER_WARP; // base row (b*1024+g)

    float* buf  = sbuf[warp];
    float* pts  = buf;          // 4 rows x 64 pts x float4
    float* vbuf = buf + 1024;   // v[96][4] row-interleaved

    // ---- Stage the 4 rows' 8x8 point blocks into smem as float4 per point ----
    const int ld3 = lane / 3, lm3 = lane - ld3 * 3;  // for lane<24 staging; reused in tail
    #pragma unroll
    for (int q = 0; q < ROWS_PER_WARP; q++) {
        const int row = wrow + q;
        const int b = row >> 10, g = row & 1023;
        const int gi = g >> 5, gj = g & 31;
        const float* base = pgi + ((size_t)b * 65536 + (size_t)(gi * 8) * 256 + (size_t)(gj * 8)) * 3;
        if (lane < 24) {
            #pragma unroll
            for (int gr = 0; gr < 8; gr++) {
                float val = base[(size_t)gr * 768 + lane];
                pts[q * 256 + (gr * 8 + ld3) * 4 + lm3] = val;  // pts[q][p].{x,y,z}
            }
        }
    }
    __syncwarp();

    // ---- Lift (lane = channel). leaky is monotone: take ring-max of raw h, leaky once. ----
    {
        const float w0 = __ldg(W_lift + lane);
        const float w1 = __ldg(W_lift + 32 + lane);
        const float w2 = __ldg(W_lift + 64 + lane);
        const float bl = __ldg(b_lift + lane);
        #pragma unroll
        for (int q = 0; q < ROWS_PER_WARP; q++) {
            const float4* P = (const float4*)(pts + q * 256);
            float mi = -3.0e38f, mt = -3.0e38f, mo = -3.0e38f;
            #pragma unroll
            for (int p = 0; p < 64; p++) {
                const int r = p >> 3, c = p & 7;
                const float4 pt = P[p];
                const float h = fmaf(pt.x, w0, fmaf(pt.y, w1, fmaf(pt.z, w2, bl)));
                const int d = min(min(r, c), min(7 - r, 7 - c));
                if (d == 3)      mi = fmaxf(mi, h);
                else if (d == 2) mt = fmaxf(mt, h);
                else             mo = fmaxf(mo, h);
            }
            vbuf[lane * 4 + q]        = leaky02(mi);
            vbuf[(32 + lane) * 4 + q] = leaky02(mt);
            vbuf[(64 + lane) * 4 + q] = leaky02(mo);
        }
    }
    __syncwarp();

    // ---- v_code[128] = leaky(v @ W_code + b); lane owns j = lane+32o; rows packed f32x2 ----
    u64 acc[4][2];
    #pragma unroll
    for (int o = 0; o < 4; o++) {
        const float b = __ldg(b_code + 32 * o + lane);
        acc[o][0] = pack2(b, b);
        acc[o][1] = acc[o][0];
    }
    #pragma unroll 6
    for (int i = 0; i < 96; i++) {
        const ulonglong2 v = *(const ulonglong2*)(vbuf + i * 4);  // (q0,q1),(q2,q3)
        const float* wr = W_code + i * 128 + lane;
        #pragma unroll
        for (int o = 0; o < 4; o++) {
            const u64 w2 = pack2(__ldg(wr + 32 * o), __ldg(wr + 32 * o));
            acc[o][0] = fma2(v.x, w2, acc[o][0]);
            acc[o][1] = fma2(v.y, w2, acc[o][1]);
        }
    }
    float* abuf = buf;  // activations [128][4]; pts region is dead now (all lanes past lift+W_code)
    #pragma unroll
    for (int o = 0; o < 4; o++) {
        float x0, x1, x2, x3;
        unpack2(acc[o][0], x0, x1);
        unpack2(acc[o][1], x2, x3);
        float4 r;
        r.x = leaky02(x0); r.y = leaky02(x1); r.z = leaky02(x2); r.w = leaky02(x3);
        *(float4*)(abuf + (32 * o + lane) * 4) = r;
    }
    __syncwarp();

    // ---- h1[64] = relu(v_code @ W_h1 + b) ----
    u64 acc1[2][2];
    #pragma unroll
    for (int o = 0; o < 2; o++) {
        const float b = __ldg(b_h1 + 32 * o + lane);
        acc1[o][0] = pack2(b, b);
        acc1[o][1] = acc1[o][0];
    }
    #pragma unroll 8
    for (int i = 0; i < 128; i++) {
        const ulonglong2 v = *(const ulonglong2*)(abuf + i * 4);
        const float* wr = W_h1 + i * 64 + lane;
        #pragma unroll
        for (int o = 0; o < 2; o++) {
            const u64 w2 = pack2(__ldg(wr + 32 * o), __ldg(wr + 32 * o));
            acc1[o][0] = fma2(v.x, w2, acc1[o][0]);
            acc1[o][1] = fma2(v.y, w2, acc1[o][1]);
        }
    }
    float* h1buf = buf + 1024;  // overwrite vbuf (all lanes past W_code reads)
    #pragma unroll
    for (int o = 0; o < 2; o++) {
        float x0, x1, x2, x3;
        unpack2(acc1[o][0], x0, x1);
        unpack2(acc1[o][1], x2, x3);
        float4 r;
        r.x = fmaxf(x0, 0.f); r.y = fmaxf(x1, 0.f); r.z = fmaxf(x2, 0.f); r.w = fmaxf(x3, 0.f);
        *(float4*)(h1buf + (32 * o + lane) * 4) = r;
    }
    __syncwarp();

    // ---- h2[32] = relu(h1 @ W_h2 + b) ----
    u64 acc2[2];
    {
        const float b = __ldg(b_h2 + lane);
        acc2[0] = pack2(b, b);
        acc2[1] = acc2[0];
    }
    #pragma unroll 8
    for (int i = 0; i < 64; i++) {
        const ulonglong2 v = *(const ulonglong2*)(h1buf + i * 4);
        const u64 w2 = pack2(__ldg(W_h2 + i * 32 + lane), __ldg(W_h2 + i * 32 + lane));
        acc2[0] = fma2(v.x, w2, acc2[0]);
        acc2[1] = fma2(v.y, w2, acc2[1]);
    }
    float* h2buf = buf;  // [32][4]
    {
        float x0, x1, x2, x3;
        unpack2(acc2[0], x0, x1);
        unpack2(acc2[1], x2, x3);
        float4 r;
        r.x = fmaxf(x0, 0.f); r.y = fmaxf(x1, 0.f); r.z = fmaxf(x2, 0.f); r.w = fmaxf(x3, 0.f);
        *(float4*)(h2buf + lane * 4) = r;
    }
    __syncwarp();

    // ---- h3[16] = relu(h2 @ W_h3 + b); half-warp per row-pair ----
    {
        const int j  = lane & 15;
        const int pr = lane >> 4;   // 0 -> rows(0,1), 1 -> rows(2,3)
        u64 a3;
        {
            const float b = __ldg(b_h3 + j);
            a3 = pack2(b, b);
        }
        #pragma unroll 8
        for (int i = 0; i < 32; i++) {
            const u64 v = *(const u64*)(h2buf + i * 4 + pr * 2);
            a3 = fma2(v, pack2(__ldg(W_h3 + i * 16 + j), __ldg(W_h3 + i * 16 + j)), a3);
        }
        float x0, x1;
        unpack2(a3, x0, x1);
        float* h3buf = buf + 1024;  // [16][4]
        h3buf[j * 4 + pr * 2]     = fmaxf(x0, 0.f);
        h3buf[j * 4 + pr * 2 + 1] = fmaxf(x1, 0.f);
    }
    __syncwarp();

    // ---- out[3] per row; lanes 0..11: q = lane/3, comp = lane%3 -> coalesced 12-float store ----
    if (lane < 12) {
        const float* h3buf = buf + 1024;
        float o = __ldg(b_h4 + lm3);
        #pragma unroll
        for (int i = 0; i < 16; i++)
            o = fmaf(h3buf[i * 4 + ld3], __ldg(W_h4 + i * 3 + lm3), o);
        out[(size_t)wrow * 3 + lane] = o;
    }
}

extern "C" void kernel_launch(void* const* d_in, const int* in_sizes, int n_in,
                              void* d_out, int out_size)
{
    const float* pgi    = (const float*)d_in[0];
    const float* W_lift = (const float*)d_in[1];
    const float* b_lift = (const float*)d_in[2];
    const float* W_code = (const float*)d_in[3];
    const float* b_code = (const float*)d_in[4];
    const float* W_h1   = (const float*)d_in[5];
    const float* b_h1   = (const float*)d_in[6];
    const float* W_h2   = (const float*)d_in[7];
    const float* b_h2   = (const float*)d_in[8];
    const float* W_h3   = (const float*)d_in[9];
    const float* b_h3   = (const float*)d_in[10];
    const float* W_h4   = (const float*)d_in[11];
    const float* b_h4   = (const float*)d_in[12];
    float* out = (float*)d_out;

    // 32768 rows, 4 rows per warp, 8 warps per CTA -> 1024 CTAs
    flatnet_r4_kernel<<<1024, WARPS_PER_CTA * 32>>>(
        pgi, W_lift, b_lift, W_code, b_code,
        W_h1, b_h1, W_h2, b_h2, W_h3, b_h3, W_h4, b_h4, out);
}

// round 3
// speedup vs baseline: 2.1235x; 1.0914x over previous
#include <cuda_runtime.h>
#include <cuda_bf16.h>
#include <cstdint>

#define WARPS_PER_CTA 2
#define ROWS_PER_WARP 8
// per-warp scratch layout (floats):
// [0,1024)    ptsXY: pair P(0..3), point p(0..63): [x0,x1,y0,y1]        (later act[128] A/B halves)
// [1024,1536) ptsZ : pair P, point p: [z0,z1]
// [1536,1920) vbufA: ch(0..95) x rows0..3   (later h1A[64]x4, h3A[16]x4)
// [1920,2304) vbufB: ch x rows4..7          (later h1B, h3B)
#define BUF_FLOATS 2304

typedef unsigned long long u64;

__device__ __forceinline__ u64 fma2(u64 a, u64 b, u64 c) {
    u64 d;
    asm("fma.rn.f32x2 %0, %1, %2, %3;" : "=l"(d) : "l"(a), "l"(b), "l"(c));
    return d;
}
__device__ __forceinline__ u64 pack2(float x, float y) {
    u64 d;
    asm("mov.b64 %0, {%1, %2};" : "=l"(d) : "r"(__float_as_uint(x)), "r"(__float_as_uint(y)));
    return d;
}
__device__ __forceinline__ void unpack2(u64 a, float& x, float& y) {
    unsigned lo, hi;
    asm("mov.b64 {%0, %1}, %2;" : "=r"(lo), "=r"(hi) : "l"(a));
    x = __uint_as_float(lo); y = __uint_as_float(hi);
}
__device__ __forceinline__ float leaky02(float x) { return fmaxf(x, 0.2f * x); }

__global__ __launch_bounds__(WARPS_PER_CTA * 32)
void flatnet_r8_kernel(
    const float* __restrict__ pgi,
    const float* __restrict__ W_lift, const float* __restrict__ b_lift,
    const float* __restrict__ W_code, const float* __restrict__ b_code,
    const float* __restrict__ W_h1,   const float* __restrict__ b_h1,
    const float* __restrict__ W_h2,   const float* __restrict__ b_h2,
    const float* __restrict__ W_h3,   const float* __restrict__ b_h3,
    const float* __restrict__ W_h4,   const float* __restrict__ b_h4,
    float* __restrict__ out)
{
    __shared__ __align__(16) float sbuf[WARPS_PER_CTA][BUF_FLOATS];

    const int warp = threadIdx.x >> 5;
    const int lane = threadIdx.x & 31;
    const int wrow = (blockIdx.x * WARPS_PER_CTA + warp) * ROWS_PER_WARP; // base row = b*1024+g
    float* buf = sbuf[warp];

    const int ld3 = lane / 3, lm3 = lane - ld3 * 3;

    // ---- Stage 8 rows' 8x8 point blocks into packed-pair layout ----
    {
        const int b = wrow >> 10, g = wrow & 1023;
        const int gi = g >> 5, gj = g & 31;          // gj..gj+7 never crosses 31 (wrow mult of 8)
        const float* base = pgi + ((size_t)b * 65536 + (size_t)(gi * 8) * 256 + (size_t)(gj * 8)) * 3;
        if (lane < 24) {
            #pragma unroll
            for (int q = 0; q < ROWS_PER_WARP; q++) {
                const int P = q >> 1, s = q & 1;
                const float* bq = base + q * 24;
                #pragma unroll
                for (int gr = 0; gr < 8; gr++) {
                    const float val = bq[(size_t)gr * 768 + lane];
                    const int p = gr * 8 + ld3;
                    int off;
                    if (lm3 == 2) off = 1024 + P * 128 + p * 2 + s;       // z
                    else          off = P * 256 + p * 4 + lm3 * 2 + s;    // x / y
                    buf[off] = val;
                }
            }
        }
    }
    __syncwarp();

    // ---- Lift (lane = channel), row-pairs packed in f32x2 ----
    {
        const float w0 = __ldg(W_lift + lane);
        const float w1 = __ldg(W_lift + 32 + lane);
        const float w2 = __ldg(W_lift + 64 + lane);
        const float bl = __ldg(b_lift + lane);
        const u64 ww0 = pack2(w0, w0), ww1 = pack2(w1, w1), ww2 = pack2(w2, w2), bb = pack2(bl, bl);

        #pragma unroll
        for (int P = 0; P < 4; P++) {
            const float* XY = buf + P * 256;
            const float* Z  = buf + 1024 + P * 128;
            float mi0 = -3.0e38f, mi1 = -3.0e38f;
            float mt0 = -3.0e38f, mt1 = -3.0e38f;
            float mo0 = -3.0e38f, mo1 = -3.0e38f;
            #pragma unroll
            for (int p = 0; p < 64; p += 2) {
                const ulonglong2 xyA = *(const ulonglong2*)(XY + p * 4);
                const ulonglong2 xyB = *(const ulonglong2*)(XY + p * 4 + 4);
                const ulonglong2 zz  = *(const ulonglong2*)(Z + p * 2);
                const u64 hA = fma2(xyA.x, ww0, fma2(xyA.y, ww1, fma2(zz.x, ww2, bb)));
                const u64 hB = fma2(xyB.x, ww0, fma2(xyB.y, ww1, fma2(zz.y, ww2, bb)));
                {
                    const int r = p >> 3, c = p & 7;
                    const int d = min(min(r, c), min(7 - r, 7 - c));
                    float h0, h1; unpack2(hA, h0, h1);
                    if (d == 3)      { mi0 = fmaxf(mi0, h0); mi1 = fmaxf(mi1, h1); }
                    else if (d == 2) { mt0 = fmaxf(mt0, h0); mt1 = fmaxf(mt1, h1); }
                    else             { mo0 = fmaxf(mo0, h0); mo1 = fmaxf(mo1, h1); }
                }
                {
                    const int r = (p + 1) >> 3, c = (p + 1) & 7;
                    const int d = min(min(r, c), min(7 - r, 7 - c));
                    float h0, h1; unpack2(hB, h0, h1);
                    if (d == 3)      { mi0 = fmaxf(mi0, h0); mi1 = fmaxf(mi1, h1); }
                    else if (d == 2) { mt0 = fmaxf(mt0, h0); mt1 = fmaxf(mt1, h1); }
                    else             { mo0 = fmaxf(mo0, h0); mo1 = fmaxf(mo1, h1); }
                }
            }
            float* vdst = buf + ((P < 2) ? 1536 : 1920);
            const int qb = (P & 1) * 2;
            vdst[lane * 4 + qb]            = leaky02(mi0);
            vdst[lane * 4 + qb + 1]        = leaky02(mi1);
            vdst[(32 + lane) * 4 + qb]     = leaky02(mt0);
            vdst[(32 + lane) * 4 + qb + 1] = leaky02(mt1);
            vdst[(64 + lane) * 4 + qb]     = leaky02(mo0);
            vdst[(64 + lane) * 4 + qb + 1] = leaky02(mo1);
        }
    }
    __syncwarp();

    // ---- v_code[128] = leaky(v @ W_code + b); lane owns j=lane+32o; 8 rows packed ----
    {
        u64 aA[4][2], aB[4][2];
        #pragma unroll
        for (int o = 0; o < 4; o++) {
            const float b = __ldg(b_code + 32 * o + lane);
            aA[o][0] = pack2(b, b); aA[o][1] = aA[o][0];
            aB[o][0] = aA[o][0];    aB[o][1] = aA[o][0];
        }
        #pragma unroll 4
        for (int i = 0; i < 96; i++) {
            const ulonglong2 vA = *(const ulonglong2*)(buf + 1536 + i * 4);
            const ulonglong2 vB = *(const ulonglong2*)(buf + 1920 + i * 4);
            const float* wr = W_code + i * 128 + lane;
            #pragma unroll
            for (int o = 0; o < 4; o++) {
                const float w = __ldg(wr + 32 * o);
                const u64 ww = pack2(w, w);
                aA[o][0] = fma2(vA.x, ww, aA[o][0]);
                aA[o][1] = fma2(vA.y, ww, aA[o][1]);
                aB[o][0] = fma2(vB.x, ww, aB[o][0]);
                aB[o][1] = fma2(vB.y, ww, aB[o][1]);
            }
        }
        __syncwarp();
        #pragma unroll
        for (int o = 0; o < 4; o++) {
            const int ch = 32 * o + lane;
            float x0, x1, x2, x3;
            unpack2(aA[o][0], x0, x1); unpack2(aA[o][1], x2, x3);
            float4 rA = {leaky02(x0), leaky02(x1), leaky02(x2), leaky02(x3)};
            *(float4*)(buf + ch * 4) = rA;                 // actA: rows 0-3
            unpack2(aB[o][0], x0, x1); unpack2(aB[o][1], x2, x3);
            float4 rB = {leaky02(x0), leaky02(x1), leaky02(x2), leaky02(x3)};
            *(float4*)(buf + 512 + ch * 4) = rB;           // actB: rows 4-7
        }
    }
    __syncwarp();

    // ---- h1[64] = relu(v_code @ W_h1 + b) ----
    {
        u64 cA[2][2], cB[2][2];
        #pragma unroll
        for (int o = 0; o < 2; o++) {
            const float b = __ldg(b_h1 + 32 * o + lane);
            cA[o][0] = pack2(b, b); cA[o][1] = cA[o][0];
            cB[o][0] = cA[o][0];    cB[o][1] = cA[o][0];
        }
        #pragma unroll 4
        for (int i = 0; i < 128; i++) {
            const ulonglong2 vA = *(const ulonglong2*)(buf + i * 4);
            const ulonglong2 vB = *(const ulonglong2*)(buf + 512 + i * 4);
            const float* wr = W_h1 + i * 64 + lane;
            #pragma unroll
            for (int o = 0; o < 2; o++) {
                const float w = __ldg(wr + 32 * o);
                const u64 ww = pack2(w, w);
                cA[o][0] = fma2(vA.x, ww, cA[o][0]);
                cA[o][1] = fma2(vA.y, ww, cA[o][1]);
                cB[o][0] = fma2(vB.x, ww, cB[o][0]);
                cB[o][1] = fma2(vB.y, ww, cB[o][1]);
            }
        }
        __syncwarp();
        #pragma unroll
        for (int o = 0; o < 2; o++) {
            const int ch = 32 * o + lane;
            float x0, x1, x2, x3;
            unpack2(cA[o][0], x0, x1); unpack2(cA[o][1], x2, x3);
            float4 rA = {fmaxf(x0,0.f), fmaxf(x1,0.f), fmaxf(x2,0.f), fmaxf(x3,0.f)};
            *(float4*)(buf + 1536 + ch * 4) = rA;          // h1A
            unpack2(cB[o][0], x0, x1); unpack2(cB[o][1], x2, x3);
            float4 rB = {fmaxf(x0,0.f), fmaxf(x1,0.f), fmaxf(x2,0.f), fmaxf(x3,0.f)};
            *(float4*)(buf + 1792 + ch * 4) = rB;          // h1B
        }
    }
    __syncwarp();

    // ---- h2[32] = relu(h1 @ W_h2 + b) ----
    {
        u64 dA[2], dB[2];
        {
            const float b = __ldg(b_h2 + lane);
            dA[0] = pack2(b, b); dA[1] = dA[0];
            dB[0] = dA[0];       dB[1] = dA[0];
        }
        #pragma unroll 8
        for (int i = 0; i < 64; i++) {
            const ulonglong2 vA = *(const ulonglong2*)(buf + 1536 + i * 4);
            const ulonglong2 vB = *(const ulonglong2*)(buf + 1792 + i * 4);
            const float w = __ldg(W_h2 + i * 32 + lane);
            const u64 ww = pack2(w, w);
            dA[0] = fma2(vA.x, ww, dA[0]);
            dA[1] = fma2(vA.y, ww, dA[1]);
            dB[0] = fma2(vB.x, ww, dB[0]);
            dB[1] = fma2(vB.y, ww, dB[1]);
        }
        __syncwarp();
        float x0, x1, x2, x3;
        unpack2(dA[0], x0, x1); unpack2(dA[1], x2, x3);
        float4 rA = {fmaxf(x0,0.f), fmaxf(x1,0.f), fmaxf(x2,0.f), fmaxf(x3,0.f)};
        *(float4*)(buf + lane * 4) = rA;                   // h2A
        unpack2(dB[0], x0, x1); unpack2(dB[1], x2, x3);
        float4 rB = {fmaxf(x0,0.f), fmaxf(x1,0.f), fmaxf(x2,0.f), fmaxf(x3,0.f)};
        *(float4*)(buf + 128 + lane * 4) = rB;             // h2B
    }
    __syncwarp();

    // ---- h3[16] = relu(h2 @ W_h3 + b); half-warp handles rows0-3 / rows4-7 ----
    {
        const int j  = lane & 15;
        const int hh = lane >> 4;
        u64 e0, e1;
        {
            const float b = __ldg(b_h3 + j);
            e0 = pack2(b, b); e1 = e0;
        }
        const float* h2p = buf + hh * 128;
        #pragma unroll 8
        for (int i = 0; i < 32; i++) {
            const ulonglong2 v = *(const ulonglong2*)(h2p + i * 4);
            const float w = __ldg(W_h3 + i * 16 + j);
            const u64 ww = pack2(w, w);
            e0 = fma2(v.x, ww, e0);
            e1 = fma2(v.y, ww, e1);
        }
        float x0, x1, x2, x3;
        unpack2(e0, x0, x1); unpack2(e1, x2, x3);
        float4 r = {fmaxf(x0,0.f), fmaxf(x1,0.f), fmaxf(x2,0.f), fmaxf(x3,0.f)};
        *(float4*)(buf + (hh ? 1600 : 1536) + j * 4) = r;  // h3A / h3B
    }
    __syncwarp();

    // ---- out[3] per row; lanes 0..23: q=lane/3, comp=lane%3 -> 24 contiguous floats ----
    if (lane < 24) {
        const float* h3p = buf + ((ld3 < 4) ? (1536 + ld3) : (1600 + (ld3 - 4)));
        float o = __ldg(b_h4 + lm3);
        #pragma unroll
        for (int i = 0; i < 16; i++)
            o = fmaf(h3p[i * 4], __ldg(W_h4 + i * 3 + lm3), o);
        out[(size_t)wrow * 3 + lane] = o;
    }
}

extern "C" void kernel_launch(void* const* d_in, const int* in_sizes, int n_in,
                              void* d_out, int out_size)
{
    const float* pgi    = (const float*)d_in[0];
    const float* W_lift = (const float*)d_in[1];
    const float* b_lift = (const float*)d_in[2];
    const float* W_code = (const float*)d_in[3];
    const float* b_code = (const float*)d_in[4];
    const float* W_h1   = (const float*)d_in[5];
    const float* b_h1   = (const float*)d_in[6];
    const float* W_h2   = (const float*)d_in[7];
    const float* b_h2   = (const float*)d_in[8];
    const float* W_h3   = (const float*)d_in[9];
    const float* b_h3   = (const float*)d_in[10];
    const float* W_h4   = (const float*)d_in[11];
    const float* b_h4   = (const float*)d_in[12];
    float* out = (float*)d_out;

    // 32768 rows, 8 rows/warp, 2 warps/CTA -> 2048 CTAs x 64 threads
    flatnet_r8_kernel<<<2048, WARPS_PER_CTA * 32>>>(
        pgi, W_lift, b_lift, W_code, b_code,
        W_h1, b_h1, W_h2, b_h2, W_h3, b_h3, W_h4, b_h4, out);
}